// round 17
// baseline (speedup 1.0000x reference)
#include <cuda_runtime.h>
#include <cstdint>

#define NB 8
#define NQ 100000
#define NC 10
#define NPB (NQ*NC)          // 1,000,000 logits per batch
#define N4B (NPB/4)          // 250,000 float4 per batch
#define NP 20
#define TOPK 100
#define CAP 32768
#define RAWTHR 0x40600000    // signed raw-bits threshold == +3.5f
#define KEY0 0xC0600000u     // sortable key of +3.5f
#define BLK 256
#define CHUNK4 1024          // float4 per stolen chunk (16KB)
#define NCHUNK 245           // ceil(250000/1024)
#define BPB 64               // blocks per batch
#define LQ 256               // per-block local queue
#define SHC 2048             // shared candidate cache (cold path)
#define ARRC 1024            // direct-rank cap

// ---- scratch (zero-initialized; finisher resets for graph replay) ----
__device__ int                g_cnt[NB];
__device__ int                g_done[NB];
__device__ int                g_ovf[NB];
__device__ int                g_work[NB];
__device__ unsigned long long g_cand[NB][CAP];

__device__ __forceinline__ unsigned int f2key(float f) {
    unsigned int u = __float_as_uint(f);
    return (u & 0x80000000u) ? ~u : (u | 0x80000000u);
}
__device__ __forceinline__ float key2f(unsigned int k) {
    unsigned int u = (k & 0x80000000u) ? (k & 0x7FFFFFFFu) : ~k;
    return __uint_as_float(u);
}
// identical set to f2key(v) >= KEY0, one signed ISETP
__device__ __forceinline__ bool iscand(float v) {
    return (int)__float_as_uint(v) >= RAWTHR;
}

// suffix-inclusive count at bin tid (256 bins), warp shuffles; blockDim=256.
__device__ __forceinline__ unsigned int suffix_of(unsigned int cntv, unsigned int* wsum) {
    const int tid = threadIdx.x, lane = tid & 31, wid = tid >> 5;
    unsigned int v = cntv;
#pragma unroll
    for (int off = 1; off < 32; off <<= 1) {
        unsigned int u = __shfl_down_sync(0xFFFFFFFFu, v, off);
        if (lane + off < 32) v += u;
    }
    if (lane == 0) wsum[wid] = v;
    __syncthreads();
    if (tid < 8) {
        unsigned int w = wsum[tid];
#pragma unroll
        for (int off = 1; off < 8; off <<= 1) {
            unsigned int u = __shfl_down_sync(0xFFu, w, off);
            if (tid + off < 8) w += u;
        }
        wsum[tid] = w;
    }
    __syncthreads();
    return v + ((wid < 7) ? wsum[wid + 1] : 0u);
}

__global__ void __launch_bounds__(BLK) fused_k(const float* __restrict__ cls,
                                               const float* __restrict__ bbox,
                                               const float* __restrict__ pts,
                                               float* __restrict__ out) {
    const int b = blockIdx.y;
    const int tid = threadIdx.x;

    __shared__ unsigned long long lq[LQ];
    __shared__ int lqn;
    __shared__ int gbase;
    __shared__ int curw;

    if (tid == 0) lqn = 0;
    __syncthreads();

    // ========== scan phase: dynamic work-stealing over 16KB chunks ==========
    {
        const float4* src = (const float4*)(cls + (size_t)b * NPB);
        while (true) {
            if (tid == 0) curw = atomicAdd(&g_work[b], 1);
            __syncthreads();
            const int w = curw;
            __syncthreads();
            if (w >= NCHUNK) break;
            const unsigned int base = (unsigned int)w * CHUNK4 + tid;
            float4 v[4]; bool ok[4];
#pragma unroll
            for (int j = 0; j < 4; j++) {
                unsigned int i = base + (unsigned int)j * BLK;
                ok[j] = (i < N4B);
                if (ok[j]) v[j] = __ldcs(src + i);
            }
#pragma unroll
            for (int j = 0; j < 4; j++) {
                if (!ok[j]) continue;
                if (iscand(v[j].x) | iscand(v[j].y) | iscand(v[j].z) | iscand(v[j].w)) {
                    const unsigned int e = (base + (unsigned int)j * BLK) * 4u;
                    float vals[4] = {v[j].x, v[j].y, v[j].z, v[j].w};
#pragma unroll
                    for (int k = 0; k < 4; k++) {
                        if (iscand(vals[k])) {
                            int p = atomicAdd(&lqn, 1);
                            if (p < LQ)
                                lq[p] = ((unsigned long long)f2key(vals[k]) << 32)
                                      | (unsigned int)(~(e + k));
                        }
                    }
                }
            }
        }
    }
    __syncthreads();

    // ---- one global reservation per block, coalesced copy-out ----
    {
        int m = lqn;
        if (m > LQ) {                       // adversarial overflow -> force fallback
            if (tid == 0) g_ovf[b] = 1;
            m = LQ;
        }
        if (tid == 0) gbase = atomicAdd(&g_cnt[b], m);
        __syncthreads();
        const int gb = gbase;
        for (int i = tid; i < m; i += BLK) {
            int pos = gb + i;
            if (pos < CAP) g_cand[b][pos] = lq[i];
        }
    }
    __syncthreads();

    // ---- last block of this batch becomes the finisher ----
    __shared__ int isLast;
    if (tid == 0) {
        __threadfence();
        isLast = (atomicAdd(&g_done[b], 1) == BPB - 1);
    }
    __syncthreads();
    if (!isLast) return;
    if (tid == 0) __threadfence();
    __syncthreads();

    // ================= finisher phase (256 threads) =================
    __shared__ unsigned long long shcand[SHC];     // 16KB (cold paths / fallback hist)
    __shared__ unsigned long long arr[ARRC];       // 8KB rank set
    __shared__ unsigned long long topc[TOPK];
    __shared__ unsigned int hcnt[256];
    __shared__ unsigned int wsum[8];
    __shared__ unsigned int cut_s;
    __shared__ int nkeep, mode_s;
    __shared__ float thr_s;
    __shared__ int   qA[TOPK];
    __shared__ unsigned char mA[TOPK];

    int cnt = g_cnt[b];
    if (cnt < TOPK || cnt > CAP || g_ovf[b] != 0) {
        // ---- cold fallback (never taken on this data): exact recollect ----
        unsigned int* h4 = (unsigned int*)shcand;          // 4096 bins
        if (tid == 0) { g_cnt[b] = 0; g_ovf[b] = 0; }
        for (int t = tid; t < 4096; t += BLK) h4[t] = 0u;
        __syncthreads();
        const float* basep = cls + (size_t)b * NPB;
        for (int i = tid; i < NPB; i += BLK)
            atomicAdd(&h4[f2key(basep[i]) >> 20], 1u);
        __syncthreads();
        if (tid == 0) {
            unsigned int acc = 0; int cut = 0;
            for (int t = 4095; t >= 0; t--) { acc += h4[t]; if (acc >= TOPK) { cut = t; break; } }
            cut_s = (unsigned int)cut << 20;
        }
        __syncthreads();
        unsigned int ckf = cut_s;
        for (int i = tid; i < NPB; i += BLK) {
            unsigned int key = f2key(basep[i]);
            if (key >= ckf) {
                int pos = atomicAdd(&g_cnt[b], 1);
                if (pos < CAP)
                    g_cand[b][pos] = ((unsigned long long)key << 32)
                                   | (unsigned int)(~(unsigned int)i);
            }
        }
        __syncthreads();
        cnt = min(g_cnt[b], CAP);
        __syncthreads();
    }
    cnt = min(cnt, CAP);

    int n;   // rank-set size in arr
    if (cnt <= ARRC) {
        // ======== hot path: direct rank set, NO histograms ========
        for (int i = tid; i < cnt; i += BLK) arr[i] = g_cand[b][i];
        n = cnt;
        __syncthreads();
    } else {
        // ======== cold path: two-level cut ========
        const unsigned long long* gc = g_cand[b];
        const bool cached = (cnt <= SHC);
        if (cached) {
            for (int i = tid; i < cnt; i += BLK) shcand[i] = gc[i];
            __syncthreads();
        }
        const unsigned long long* cand = cached ? (const unsigned long long*)shcand : gc;

        hcnt[tid] = 0u;
        __syncthreads();
        for (int i = tid; i < cnt; i += BLK)
            atomicAdd(&hcnt[(unsigned int)(cand[i] >> (32 + 24))], 1u);
        __syncthreads();
        {
            unsigned int cv = hcnt[tid];
            unsigned int s = suffix_of(cv, wsum);
            if (s >= TOPK && s - cv < TOPK) cut_s = (unsigned int)tid;
        }
        __syncthreads();
        const unsigned int basek = cut_s << 24;
        __syncthreads();

        hcnt[tid] = 0u;
        __syncthreads();
        for (int i = tid; i < cnt; i += BLK) {
            unsigned int key = (unsigned int)(cand[i] >> 32);
            if (key >= basek) atomicAdd(&hcnt[min(255u, (key - basek) >> 16)], 1u);
        }
        __syncthreads();
        {
            unsigned int cv = hcnt[tid];
            unsigned int s = suffix_of(cv, wsum);
            if (s >= TOPK && s - cv < TOPK) cut_s = (unsigned int)tid;
        }
        __syncthreads();
        const unsigned int ck = basek + (cut_s << 16);

        if (tid == 0) nkeep = 0;
        __syncthreads();
        for (int i = tid; i < cnt; i += BLK) {
            unsigned long long c = cand[i];
            if ((unsigned int)(c >> 32) >= ck) {
                int p = atomicAdd(&nkeep, 1);
                if (p < ARRC) arr[p] = c;
            }
        }
        __syncthreads();
        n = nkeep;
        if (n > ARRC) {
            // degenerate ties overflow: exact rank over full candidate list
            if (tid < TOPK) topc[tid] = 0ULL;
            __syncthreads();
            for (int i = tid; i < cnt; i += BLK) {
                unsigned long long c = cand[i];
                if ((unsigned int)(c >> 32) >= ck) {
                    int rank = 0;
                    for (int j = 0; j < cnt; j++) rank += (cand[j] > c);
                    if (rank < TOPK) topc[rank] = c;
                }
            }
            n = ARRC;
            goto ranked;
        }
    }

    // ---- exact rank-by-count over arr (composites distinct -> unique ranks) ----
    if (tid < TOPK) topc[tid] = 0ULL;
    __syncthreads();
    for (int i = tid; i < n; i += BLK) {
        unsigned long long c = arr[i];
        int rank = 0;
        for (int j = 0; j < n; j++) rank += (arr[j] > c);
        if (rank < TOPK) topc[rank] = c;
    }
ranked:
    __syncthreads();

    if (tid == 0) {
        float f = key2f((unsigned int)(topc[0] >> 32));
        float maxs = 1.f / (1.f + expf(-f));
        int mode; float thr = 0.1f;
        if (maxs > 0.1f) mode = 0;
        else {
            float tmp = 0.1f; mode = 2;
            while (true) {
                tmp *= 0.9f;
                if (tmp < 0.01f) { mode = 2; break; }
                if (maxs >= tmp) { mode = 1; thr = tmp; break; }
            }
        }
        mode_s = mode; thr_s = thr;
    }
    __syncthreads();

    // output layout (float32, tuple order, C-contiguous each):
    float* oBox   = out;                       // [NB][TOPK][4]
    float* oScore = out + NB * TOPK * 4;       // [NB][TOPK]
    float* oLabel = oScore + NB * TOPK;        // [NB][TOPK]
    float* oPts   = oLabel + NB * TOPK;        // [NB][TOPK][NP][2]
    float* oMask  = oPts + NB * TOPK * NP * 2; // [NB][TOPK]

    const int nv = min(n, TOPK);               // valid ranks

    // ---- stage 1: per-rank metadata + box/score/label/mask writes ----
    if (tid < TOPK) {
        const int r = tid;
        unsigned long long c = topc[r];
        const bool valid = (r < nv);
        float score = 0.f, x1 = 0.f, y1 = 0.f, x2 = 0.f, y2 = 0.f;
        int label = 0, q = 0;
        bool mask = false;
        if (valid) {
            unsigned int key = (unsigned int)(c >> 32);
            unsigned int idx = ~(unsigned int)(c & 0xFFFFFFFFu);
            float f = key2f(key);
            score = 1.f / (1.f + expf(-f));
            label = (int)(idx % NC);
            q     = (int)(idx / NC);
            const float4 bb = __ldg((const float4*)(bbox + ((size_t)b * NQ + q) * 4));
            float cx = bb.x, cy = bb.y, w = bb.z, h = bb.w;
            x1 = (cx - w * 0.5f) * 30.f - 15.f;
            y1 = (cy - h * 0.5f) * 60.f - 30.f;
            x2 = (cx + w * 0.5f) * 30.f - 15.f;
            y2 = (cy + h * 0.5f) * 60.f - 30.f;
            bool rmask = x1 >= -20.f && y1 >= -35.f && x2 >= -20.f && y2 >= -35.f
                      && x1 <=  20.f && y1 <=  35.f && x2 <=  20.f && y2 <=  35.f;
            bool tm = (mode_s == 0) ? (score > 0.1f)
                    : (mode_s == 1) ? (score >= thr_s) : true;
            mask = rmask && tm;
        }
        qA[r] = q;
        mA[r] = mask ? 1 : 0;
        const size_t ob = (size_t)b * TOPK + r;
        ((float4*)oBox)[ob] = mask ? make_float4(x1, y1, x2, y2)
                                   : make_float4(0.f, 0.f, 0.f, 0.f);
        oScore[ob] = mask ? score : 0.f;
        oLabel[ob] = mask ? (float)label : 0.f;
        oMask[ob]  = mask ? 1.f : 0.f;
    }
    __syncthreads();

    // ---- stage 2: pts gather, vectorized, spread over all threads ----
    for (int t = tid; t < TOPK * 10; t += BLK) {
        const int r = t / 10, c4 = t % 10;
        const bool mk = mA[r] != 0;
        float4 o = make_float4(0.f, 0.f, 0.f, 0.f);
        if (mk) {
            const float4 v = __ldg((const float4*)(pts + ((size_t)b * NQ + qA[r]) * (NP * 2)) + c4);
            o.x = v.x * 30.f - 15.f;
            o.y = v.y * 60.f - 30.f;
            o.z = v.z * 30.f - 15.f;
            o.w = v.w * 60.f - 30.f;
        }
        ((float4*)oPts)[(size_t)b * TOPK * 10 + t] = o;
    }

    // ---- reset scratch for next graph replay ----
    __syncthreads();
    if (tid == 0) { g_cnt[b] = 0; g_done[b] = 0; g_ovf[b] = 0; g_work[b] = 0; }
}

extern "C" void kernel_launch(void* const* d_in, const int* in_sizes, int n_in,
                              void* d_out, int out_size) {
    const float* cls  = (const float*)d_in[0];   // [8,100000,10]
    const float* bbox = (const float*)d_in[1];   // [8,100000,4]
    const float* pts  = (const float*)d_in[2];   // [8,100000,20,2]
    float* out = (float*)d_out;

    dim3 grid(BPB, NB);
    fused_k<<<grid, BLK>>>(cls, bbox, pts, out);
}